// round 1
// baseline (speedup 1.0000x reference)
#include <cuda_runtime.h>
#include <math.h>

#define NN 100000
#define EE 1600000
#define GG 64

// ---------------- scratch (device globals; no allocation allowed) ----------
__device__ float  g_h[NN * 128];        // node features [N,128]
__device__ float  g_agg[NN * 128];      // (1+eps)*h + scatter(h[src]) -> dst
__device__ float  g_z[NN * 256];        // MLP hidden pre-BN
__device__ double g_sum[256];
__device__ double g_sumsq[256];
__device__ float  g_scale[256];
__device__ float  g_shift[256];
__device__ float  g_pool[2 * GG * 128];
__device__ float  g_cnt[2 * GG];
__device__ float  g_fc1o[GG * 256];
__device__ float  g_fc2o[GG * 64];

// ---------------- small utility kernels -----------------------------------
__global__ void zero_pool_kernel() {
    int i = blockIdx.x * 256 + threadIdx.x;   // grid 64 x 256 == 16384 == 2*GG*128
    g_pool[i] = 0.f;
    if (i < 2 * GG) g_cnt[i] = 0.f;
}

// g_agg = (1+eps)*g_h ; also zero BN accumulators (block 0)
__global__ void init_agg_kernel(const float* __restrict__ eps) {
    int i = blockIdx.x * 256 + threadIdx.x;   // grid 12500 x 256 float4s
    float e = 1.0f + eps[0];
    float4 v = reinterpret_cast<const float4*>(g_h)[i];
    v.x *= e; v.y *= e; v.z *= e; v.w *= e;
    reinterpret_cast<float4*>(g_agg)[i] = v;
    if (blockIdx.x == 0) { g_sum[threadIdx.x] = 0.0; g_sumsq[threadIdx.x] = 0.0; }
}

// one warp per edge: gather h[src] row (512B), vector-reduce into agg[dst]
__global__ void scatter_kernel(const int* __restrict__ ei) {
    int idx = blockIdx.x * 256 + threadIdx.x;  // grid 200000 x 256 (== E*32)
    int e = idx >> 5;
    int c = (idx & 31) << 2;
    int src = __ldg(&ei[e]);
    int dst = __ldg(&ei[EE + e]);
    float4 v = *reinterpret_cast<const float4*>(&g_h[src * 128 + c]);
    float* p = &g_agg[dst * 128 + c];
    asm volatile("red.global.add.v4.f32 [%0], {%1,%2,%3,%4};"
                 :: "l"(p), "f"(v.x), "f"(v.y), "f"(v.z), "f"(v.w) : "memory");
}

// ---------------- tiled fp32 GEMM -----------------------------------------
// MODE 0: C(g_h)[N,128]   = Aext[N,1024] @ B[1024,128] + bias        (embedding)
// MODE 1: C(g_z)[N,256]   = g_agg[N,128] @ B[128,256]  + bias        (MLP fc1, pre-BN)
// MODE 2: C(g_h)[N,128]   = relu( relu(BN(g_z))[N,256] @ B[256,128] + bias + g_h )
template <int MODE>
__global__ __launch_bounds__(256)
void gemm_kernel(const float* __restrict__ Aext,
                 const float* __restrict__ B,
                 const float* __restrict__ bias)
{
    constexpr int K  = (MODE == 0) ? 1024 : ((MODE == 1) ? 128 : 256);
    constexpr int NB = (MODE == 1) ? 256 : 128;
    const float* A = (MODE == 0) ? Aext : ((MODE == 1) ? g_agg : g_z);
    float* C = (MODE == 1) ? g_z : g_h;

    __shared__ float As[16][132];   // padded: transposed A tile
    __shared__ float Bs[16][128];

    const int tid  = threadIdx.x;
    const int bm   = blockIdx.x * 128;
    const int bn   = blockIdx.y * 128;
    const int aRow = tid >> 2;            // 0..63
    const int aCol = (tid & 3) << 2;      // 0,4,8,12
    const int bRow = tid >> 5;            // 0..7
    const int bCol = (tid & 31) << 2;     // 0..124
    const int ty   = tid >> 4;            // 0..15
    const int tx   = tid & 15;            // 0..15

    float acc[8][8];
#pragma unroll
    for (int i = 0; i < 8; i++)
#pragma unroll
        for (int j = 0; j < 8; j++) acc[i][j] = 0.f;

    for (int k0 = 0; k0 < K; k0 += 16) {
#pragma unroll
        for (int p = 0; p < 2; p++) {
            int r = bm + aRow + p * 64;
            float4 v = make_float4(0.f, 0.f, 0.f, 0.f);
            if (r < NN)
                v = *reinterpret_cast<const float4*>(&A[(size_t)r * K + k0 + aCol]);
            if (MODE == 2) {   // BN + ReLU applied on the fly to GEMM2 input
                int kk = k0 + aCol;
                v.x = fmaxf(fmaf(v.x, g_scale[kk + 0], g_shift[kk + 0]), 0.f);
                v.y = fmaxf(fmaf(v.y, g_scale[kk + 1], g_shift[kk + 1]), 0.f);
                v.z = fmaxf(fmaf(v.z, g_scale[kk + 2], g_shift[kk + 2]), 0.f);
                v.w = fmaxf(fmaf(v.w, g_scale[kk + 3], g_shift[kk + 3]), 0.f);
            }
            As[aCol + 0][aRow + p * 64] = v.x;
            As[aCol + 1][aRow + p * 64] = v.y;
            As[aCol + 2][aRow + p * 64] = v.z;
            As[aCol + 3][aRow + p * 64] = v.w;
        }
#pragma unroll
        for (int p = 0; p < 2; p++) {
            int kr = k0 + bRow + p * 8;
            *reinterpret_cast<float4*>(&Bs[bRow + p * 8][bCol]) =
                *reinterpret_cast<const float4*>(&B[(size_t)kr * NB + bn + bCol]);
        }
        __syncthreads();
#pragma unroll
        for (int kk = 0; kk < 16; kk++) {
            float a[8], b[8];
            *reinterpret_cast<float4*>(a)     = *reinterpret_cast<const float4*>(&As[kk][ty * 8]);
            *reinterpret_cast<float4*>(a + 4) = *reinterpret_cast<const float4*>(&As[kk][ty * 8 + 4]);
            *reinterpret_cast<float4*>(b)     = *reinterpret_cast<const float4*>(&Bs[kk][tx * 8]);
            *reinterpret_cast<float4*>(b + 4) = *reinterpret_cast<const float4*>(&Bs[kk][tx * 8 + 4]);
#pragma unroll
            for (int i = 0; i < 8; i++)
#pragma unroll
                for (int j = 0; j < 8; j++)
                    acc[i][j] = fmaf(a[i], b[j], acc[i][j]);
        }
        __syncthreads();
    }

#pragma unroll
    for (int i = 0; i < 8; i++) {
        int r = bm + ty * 8 + i;
        if (r < NN) {
#pragma unroll
            for (int j = 0; j < 8; j += 4) {
                int c = bn + tx * 8 + j;
                float4 v;
                v.x = acc[i][j + 0] + bias[c + 0];
                v.y = acc[i][j + 1] + bias[c + 1];
                v.z = acc[i][j + 2] + bias[c + 2];
                v.w = acc[i][j + 3] + bias[c + 3];
                if (MODE == 2) {   // residual + ReLU
                    float4 h = *reinterpret_cast<const float4*>(&g_h[(size_t)r * 128 + c]);
                    v.x = fmaxf(v.x + h.x, 0.f);
                    v.y = fmaxf(v.y + h.y, 0.f);
                    v.z = fmaxf(v.z + h.z, 0.f);
                    v.w = fmaxf(v.w + h.w, 0.f);
                }
                *reinterpret_cast<float4*>(&C[(size_t)r * NB + c]) = v;
            }
        }
    }
}

// ---------------- BatchNorm statistics ------------------------------------
__global__ void bn_stats_kernel() {     // grid 391 x 256
    int col = threadIdx.x;
    int r0 = blockIdx.x * 256;
    int r1 = min(r0 + 256, NN);
    float s = 0.f, s2 = 0.f;
    for (int r = r0; r < r1; r++) {
        float v = g_z[(size_t)r * 256 + col];
        s += v;
        s2 = fmaf(v, v, s2);
    }
    atomicAdd(&g_sum[col], (double)s);
    atomicAdd(&g_sumsq[col], (double)s2);
}

__global__ void bn_finalize_kernel(const float* __restrict__ gam,
                                   const float* __restrict__ bet) {
    int c = threadIdx.x;   // 256
    float mean = (float)(g_sum[c] / (double)NN);
    float var  = (float)(g_sumsq[c] / (double)NN) - mean * mean;
    float sc = gam[c] * rsqrtf(var + 1e-5f);
    g_scale[c] = sc;
    g_shift[c] = fmaf(-mean, sc, bet[c]);
}

// ---------------- global mean pool ----------------------------------------
__global__ void pool_kernel(const int* __restrict__ batch, int which) {
    int idx = blockIdx.x * 256 + threadIdx.x;   // grid 12500 x 256 (== N*32)
    int n = idx >> 5;
    int c = (idx & 31) << 2;
    int g = __ldg(&batch[n]);
    float4 v = *reinterpret_cast<const float4*>(&g_h[n * 128 + c]);
    float* p = &g_pool[(which * GG + g) * 128 + c];
    asm volatile("red.global.add.v4.f32 [%0], {%1,%2,%3,%4};"
                 :: "l"(p), "f"(v.x), "f"(v.y), "f"(v.z), "f"(v.w) : "memory");
    if ((idx & 31) == 0) atomicAdd(&g_cnt[which * GG + g], 1.0f);
}

// ---------------- head ----------------------------------------------------
__global__ void head1_kernel(const float* __restrict__ W, const float* __restrict__ b) {
    int g = blockIdx.x, j = threadIdx.x;   // 64 x 256
    __shared__ float xc[256];
    if (j < 128) xc[j] = g_pool[g * 128 + j] / fmaxf(g_cnt[g], 1.0f);
    else         xc[j] = g_pool[(GG + g) * 128 + (j - 128)] / fmaxf(g_cnt[GG + g], 1.0f);
    __syncthreads();
    float acc = b[j];
#pragma unroll 8
    for (int k = 0; k < 256; k++) acc = fmaf(xc[k], W[k * 256 + j], acc);
    g_fc1o[g * 256 + j] = fmaxf(acc, 0.f);
}

__global__ void head2_kernel(const float* __restrict__ W, const float* __restrict__ b) {
    int g = blockIdx.x, j = threadIdx.x;   // 64 x 64
    __shared__ float xin[256];
    for (int k = j; k < 256; k += 64) xin[k] = g_fc1o[g * 256 + k];
    __syncthreads();
    float acc = b[j];
#pragma unroll 8
    for (int k = 0; k < 256; k++) acc = fmaf(xin[k], W[k * 64 + j], acc);
    g_fc2o[g * 64 + j] = fmaxf(acc, 0.f);
}

__global__ void head3_kernel(const float* __restrict__ W, const float* __restrict__ b,
                             float* __restrict__ out) {
    int g = threadIdx.x;   // 1 x 64
    float acc = b[0];
#pragma unroll
    for (int k = 0; k < 64; k++) acc = fmaf(g_fc2o[g * 64 + k], W[k], acc);
    out[g] = 1.0f / (1.0f + expf(-acc));
}

// ---------------- orchestration -------------------------------------------
extern "C" void kernel_launch(void* const* d_in, const int* in_sizes, int n_in,
                              void* d_out, int out_size) {
    const float* x[2]     = { (const float*)d_in[0], (const float*)d_in[3] };
    const int*   ei[2]    = { (const int*)d_in[1],   (const int*)d_in[4] };
    const int*   batch[2] = { (const int*)d_in[2],   (const int*)d_in[5] };

    const int GRID_M = (NN + 127) / 128;   // 782

    zero_pool_kernel<<<64, 256>>>();

    for (int b = 0; b < 2; b++) {
        int o = 6 + b * 9;
        const float* embW = (const float*)d_in[o + 0];
        const float* embB = (const float*)d_in[o + 1];
        const float* W1   = (const float*)d_in[o + 2];
        const float* b1   = (const float*)d_in[o + 3];
        const float* gam  = (const float*)d_in[o + 4];
        const float* bet  = (const float*)d_in[o + 5];
        const float* W2   = (const float*)d_in[o + 6];
        const float* b2   = (const float*)d_in[o + 7];
        const float* eps  = (const float*)d_in[o + 8];

        // embedding: h = x @ embW + embB
        gemm_kernel<0><<<dim3(GRID_M, 1), 256>>>(x[b], embW, embB);

        for (int i = 0; i < 4; i++) {
            init_agg_kernel<<<12500, 256>>>(eps + i);
            scatter_kernel<<<200000, 256>>>(ei[b]);
            gemm_kernel<1><<<dim3(GRID_M, 2), 256>>>(nullptr, W1 + (size_t)i * 128 * 256,
                                                     b1 + i * 256);
            bn_stats_kernel<<<391, 256>>>();
            bn_finalize_kernel<<<1, 256>>>(gam + i * 256, bet + i * 256);
            gemm_kernel<2><<<dim3(GRID_M, 1), 256>>>(nullptr, W2 + (size_t)i * 256 * 128,
                                                     b2 + i * 128);
        }
        pool_kernel<<<12500, 256>>>(batch[b], b);
    }

    head1_kernel<<<64, 256>>>((const float*)d_in[24], (const float*)d_in[25]);
    head2_kernel<<<64, 64>>>((const float*)d_in[26], (const float*)d_in[27]);
    head3_kernel<<<1, 64>>>((const float*)d_in[28], (const float*)d_in[29], (float*)d_out);
}

// round 2
// speedup vs baseline: 1.0039x; 1.0039x over previous
#include <cuda_runtime.h>
#include <math.h>

#define NN 100000
#define EE 1600000
#define GG 64

// ---------------- scratch (device globals; no allocation allowed) ----------
__device__ float  g_h[NN * 128];        // node features [N,128]
__device__ float  g_agg[NN * 128];      // (1+eps)*h + scatter(h[src]) -> dst
__device__ float  g_z[NN * 256];        // MLP hidden pre-BN
__device__ double g_sum[256];
__device__ double g_sumsq[256];
__device__ float  g_scale[256];
__device__ float  g_shift[256];
__device__ float  g_pool[2 * GG * 128];
__device__ float  g_cnt[2 * GG];
__device__ float  g_fc1o[GG * 256];
__device__ float  g_fc2o[GG * 64];

// ---------------- f32x2 packed-math helpers --------------------------------
typedef unsigned long long u64;

__device__ __forceinline__ u64 pack2(float lo, float hi) {
    u64 r; asm("mov.b64 %0, {%1, %2};" : "=l"(r) : "f"(lo), "f"(hi)); return r;
}
__device__ __forceinline__ float2 unpack2(u64 v) {
    float2 r; asm("mov.b64 {%0, %1}, %2;" : "=f"(r.x), "=f"(r.y) : "l"(v)); return r;
}
__device__ __forceinline__ void fma2(u64& d, u64 a, u64 b) {
    asm("fma.rn.f32x2 %0, %1, %2, %0;" : "+l"(d) : "l"(a), "l"(b));
}

// ---------------- small utility kernels -----------------------------------
__global__ void zero_pool_kernel() {
    int i = blockIdx.x * 256 + threadIdx.x;   // grid 64 x 256 == 16384 == 2*GG*128
    g_pool[i] = 0.f;
    if (i < 2 * GG) g_cnt[i] = 0.f;
}

// g_agg = (1+eps)*g_h ; also zero BN accumulators (block 0)
__global__ void init_agg_kernel(const float* __restrict__ eps) {
    int i = blockIdx.x * 256 + threadIdx.x;   // grid 12500 x 256 float4s
    float e = 1.0f + eps[0];
    float4 v = reinterpret_cast<const float4*>(g_h)[i];
    v.x *= e; v.y *= e; v.z *= e; v.w *= e;
    reinterpret_cast<float4*>(g_agg)[i] = v;
    if (blockIdx.x == 0) { g_sum[threadIdx.x] = 0.0; g_sumsq[threadIdx.x] = 0.0; }
}

// one warp per edge: gather h[src] row (512B), vector-reduce into agg[dst]
__global__ void scatter_kernel(const int* __restrict__ ei) {
    int idx = blockIdx.x * 256 + threadIdx.x;  // grid 200000 x 256 (== E*32)
    int e = idx >> 5;
    int c = (idx & 31) << 2;
    int src = __ldg(&ei[e]);
    int dst = __ldg(&ei[EE + e]);
    float4 v = *reinterpret_cast<const float4*>(&g_h[src * 128 + c]);
    float* p = &g_agg[dst * 128 + c];
    asm volatile("red.global.add.v4.f32 [%0], {%1,%2,%3,%4};"
                 :: "l"(p), "f"(v.x), "f"(v.y), "f"(v.z), "f"(v.w) : "memory");
}

// ---------------- tiled fp32 GEMM (packed f32x2 inner loop) -----------------
// MODE 0: C(g_h)[N,128]   = Aext[N,1024] @ B[1024,128] + bias        (embedding)
// MODE 1: C(g_z)[N,256]   = g_agg[N,128] @ B[128,256]  + bias        (MLP fc1, pre-BN)
// MODE 2: C(g_h)[N,128]   = relu( relu(BN(g_z))[N,256] @ B[256,128] + bias + g_h )
template <int MODE>
__global__ __launch_bounds__(256)
void gemm_kernel(const float* __restrict__ Aext,
                 const float* __restrict__ B,
                 const float* __restrict__ bias)
{
    constexpr int K  = (MODE == 0) ? 1024 : ((MODE == 1) ? 128 : 256);
    constexpr int NB = (MODE == 1) ? 256 : 128;
    const float* A = (MODE == 0) ? Aext : ((MODE == 1) ? g_agg : g_z);
    float* C = (MODE == 1) ? g_z : g_h;

    __shared__ float As[16][132];   // padded: transposed A tile
    __shared__ float Bs[16][128];

    const int tid  = threadIdx.x;
    const int bm   = blockIdx.x * 128;
    const int bn   = blockIdx.y * 128;
    const int aRow = tid >> 2;            // 0..63
    const int aCol = (tid & 3) << 2;      // 0,4,8,12
    const int bRow = tid >> 5;            // 0..7
    const int bCol = (tid & 31) << 2;     // 0..124
    const int ty   = tid >> 4;            // 0..15
    const int tx   = tid & 15;            // 0..15

    u64 acc2[8][4];                        // [i][j-pair], pair = cols (2j, 2j+1)
#pragma unroll
    for (int i = 0; i < 8; i++)
#pragma unroll
        for (int j = 0; j < 4; j++) acc2[i][j] = 0ull;

    for (int k0 = 0; k0 < K; k0 += 16) {
#pragma unroll
        for (int p = 0; p < 2; p++) {
            int r = bm + aRow + p * 64;
            float4 v = make_float4(0.f, 0.f, 0.f, 0.f);
            if (r < NN)
                v = *reinterpret_cast<const float4*>(&A[(size_t)r * K + k0 + aCol]);
            if (MODE == 2) {   // BN + ReLU applied on the fly to GEMM2 input
                int kk = k0 + aCol;
                v.x = fmaxf(fmaf(v.x, g_scale[kk + 0], g_shift[kk + 0]), 0.f);
                v.y = fmaxf(fmaf(v.y, g_scale[kk + 1], g_shift[kk + 1]), 0.f);
                v.z = fmaxf(fmaf(v.z, g_scale[kk + 2], g_shift[kk + 2]), 0.f);
                v.w = fmaxf(fmaf(v.w, g_scale[kk + 3], g_shift[kk + 3]), 0.f);
            }
            As[aCol + 0][aRow + p * 64] = v.x;
            As[aCol + 1][aRow + p * 64] = v.y;
            As[aCol + 2][aRow + p * 64] = v.z;
            As[aCol + 3][aRow + p * 64] = v.w;
        }
#pragma unroll
        for (int p = 0; p < 2; p++) {
            int kr = k0 + bRow + p * 8;
            *reinterpret_cast<float4*>(&Bs[bRow + p * 8][bCol]) =
                *reinterpret_cast<const float4*>(&B[(size_t)kr * NB + bn + bCol]);
        }
        __syncthreads();
#pragma unroll
        for (int kk = 0; kk < 16; kk++) {
            float a[8];
            *reinterpret_cast<float4*>(a)     = *reinterpret_cast<const float4*>(&As[kk][ty * 8]);
            *reinterpret_cast<float4*>(a + 4) = *reinterpret_cast<const float4*>(&As[kk][ty * 8 + 4]);
            // B pairs load directly as packed f32x2 (adjacent floats in smem)
            const u64* pb = reinterpret_cast<const u64*>(&Bs[kk][tx * 8]);
            u64 b2[4];
            b2[0] = pb[0]; b2[1] = pb[1]; b2[2] = pb[2]; b2[3] = pb[3];
            u64 a2[8];
#pragma unroll
            for (int i = 0; i < 8; i++) a2[i] = pack2(a[i], a[i]);
#pragma unroll
            for (int i = 0; i < 8; i++)
#pragma unroll
                for (int j = 0; j < 4; j++)
                    fma2(acc2[i][j], a2[i], b2[j]);
        }
        __syncthreads();
    }

#pragma unroll
    for (int i = 0; i < 8; i++) {
        int r = bm + ty * 8 + i;
        if (r < NN) {
#pragma unroll
            for (int jj = 0; jj < 2; jj++) {   // two float4 stores of 8 cols
                int c = bn + tx * 8 + jj * 4;
                float2 p0 = unpack2(acc2[i][jj * 2 + 0]);
                float2 p1 = unpack2(acc2[i][jj * 2 + 1]);
                float4 v;
                v.x = p0.x + bias[c + 0];
                v.y = p0.y + bias[c + 1];
                v.z = p1.x + bias[c + 2];
                v.w = p1.y + bias[c + 3];
                if (MODE == 2) {   // residual + ReLU
                    float4 h = *reinterpret_cast<const float4*>(&g_h[(size_t)r * 128 + c]);
                    v.x = fmaxf(v.x + h.x, 0.f);
                    v.y = fmaxf(v.y + h.y, 0.f);
                    v.z = fmaxf(v.z + h.z, 0.f);
                    v.w = fmaxf(v.w + h.w, 0.f);
                }
                *reinterpret_cast<float4*>(&C[(size_t)r * NB + c]) = v;
            }
        }
    }
}

// ---------------- BatchNorm statistics ------------------------------------
__global__ void bn_stats_kernel() {     // grid 391 x 256
    int col = threadIdx.x;
    int r0 = blockIdx.x * 256;
    int r1 = min(r0 + 256, NN);
    float s = 0.f, s2 = 0.f;
    for (int r = r0; r < r1; r++) {
        float v = g_z[(size_t)r * 256 + col];
        s += v;
        s2 = fmaf(v, v, s2);
    }
    atomicAdd(&g_sum[col], (double)s);
    atomicAdd(&g_sumsq[col], (double)s2);
}

__global__ void bn_finalize_kernel(const float* __restrict__ gam,
                                   const float* __restrict__ bet) {
    int c = threadIdx.x;   // 256
    float mean = (float)(g_sum[c] / (double)NN);
    float var  = (float)(g_sumsq[c] / (double)NN) - mean * mean;
    float sc = gam[c] * rsqrtf(var + 1e-5f);
    g_scale[c] = sc;
    g_shift[c] = fmaf(-mean, sc, bet[c]);
}

// ---------------- global mean pool ----------------------------------------
__global__ void pool_kernel(const int* __restrict__ batch, int which) {
    int idx = blockIdx.x * 256 + threadIdx.x;   // grid 12500 x 256 (== N*32)
    int n = idx >> 5;
    int c = (idx & 31) << 2;
    int g = __ldg(&batch[n]);
    float4 v = *reinterpret_cast<const float4*>(&g_h[n * 128 + c]);
    float* p = &g_pool[(which * GG + g) * 128 + c];
    asm volatile("red.global.add.v4.f32 [%0], {%1,%2,%3,%4};"
                 :: "l"(p), "f"(v.x), "f"(v.y), "f"(v.z), "f"(v.w) : "memory");
    if ((idx & 31) == 0) atomicAdd(&g_cnt[which * GG + g], 1.0f);
}

// ---------------- head ----------------------------------------------------
__global__ void head1_kernel(const float* __restrict__ W, const float* __restrict__ b) {
    int g = blockIdx.x, j = threadIdx.x;   // 64 x 256
    __shared__ float xc[256];
    if (j < 128) xc[j] = g_pool[g * 128 + j] / fmaxf(g_cnt[g], 1.0f);
    else         xc[j] = g_pool[(GG + g) * 128 + (j - 128)] / fmaxf(g_cnt[GG + g], 1.0f);
    __syncthreads();
    float acc = b[j];
#pragma unroll 8
    for (int k = 0; k < 256; k++) acc = fmaf(xc[k], W[k * 256 + j], acc);
    g_fc1o[g * 256 + j] = fmaxf(acc, 0.f);
}

__global__ void head2_kernel(const float* __restrict__ W, const float* __restrict__ b) {
    int g = blockIdx.x, j = threadIdx.x;   // 64 x 64
    __shared__ float xin[256];
    for (int k = j; k < 256; k += 64) xin[k] = g_fc1o[g * 256 + k];
    __syncthreads();
    float acc = b[j];
#pragma unroll 8
    for (int k = 0; k < 256; k++) acc = fmaf(xin[k], W[k * 64 + j], acc);
    g_fc2o[g * 64 + j] = fmaxf(acc, 0.f);
}

__global__ void head3_kernel(const float* __restrict__ W, const float* __restrict__ b,
                             float* __restrict__ out) {
    int g = threadIdx.x;   // 1 x 64
    float acc = b[0];
#pragma unroll
    for (int k = 0; k < 64; k++) acc = fmaf(g_fc2o[g * 64 + k], W[k], acc);
    out[g] = 1.0f / (1.0f + expf(-acc));
}

// ---------------- orchestration -------------------------------------------
extern "C" void kernel_launch(void* const* d_in, const int* in_sizes, int n_in,
                              void* d_out, int out_size) {
    const float* x[2]     = { (const float*)d_in[0], (const float*)d_in[3] };
    const int*   ei[2]    = { (const int*)d_in[1],   (const int*)d_in[4] };
    const int*   batch[2] = { (const int*)d_in[2],   (const int*)d_in[5] };

    const int GRID_M = (NN + 127) / 128;   // 782

    zero_pool_kernel<<<64, 256>>>();

    for (int b = 0; b < 2; b++) {
        int o = 6 + b * 9;
        const float* embW = (const float*)d_in[o + 0];
        const float* embB = (const float*)d_in[o + 1];
        const float* W1   = (const float*)d_in[o + 2];
        const float* b1   = (const float*)d_in[o + 3];
        const float* gam  = (const float*)d_in[o + 4];
        const float* bet  = (const float*)d_in[o + 5];
        const float* W2   = (const float*)d_in[o + 6];
        const float* b2   = (const float*)d_in[o + 7];
        const float* eps  = (const float*)d_in[o + 8];

        // embedding: h = x @ embW + embB
        gemm_kernel<0><<<dim3(GRID_M, 1), 256>>>(x[b], embW, embB);

        for (int i = 0; i < 4; i++) {
            init_agg_kernel<<<12500, 256>>>(eps + i);
            scatter_kernel<<<200000, 256>>>(ei[b]);
            gemm_kernel<1><<<dim3(GRID_M, 2), 256>>>(nullptr, W1 + (size_t)i * 128 * 256,
                                                     b1 + i * 256);
            bn_stats_kernel<<<391, 256>>>();
            bn_finalize_kernel<<<1, 256>>>(gam + i * 256, bet + i * 256);
            gemm_kernel<2><<<dim3(GRID_M, 1), 256>>>(nullptr, W2 + (size_t)i * 256 * 128,
                                                     b2 + i * 128);
        }
        pool_kernel<<<12500, 256>>>(batch[b], b);
    }

    head1_kernel<<<64, 256>>>((const float*)d_in[24], (const float*)d_in[25]);
    head2_kernel<<<64, 64>>>((const float*)d_in[26], (const float*)d_in[27]);
    head3_kernel<<<1, 64>>>((const float*)d_in[28], (const float*)d_in[29], (float*)d_out);
}

// round 4
// speedup vs baseline: 1.2125x; 1.2078x over previous
#include <cuda_runtime.h>
#include <math.h>
#include <stdint.h>

#define NN 100000
#define EE 1600000
#define GG 64

// ---------------- scratch (device globals; no allocation allowed) ----------
__device__ float  g_h[NN * 128];
__device__ float  g_agg[NN * 128];
__device__ float  g_z[NN * 256];
__device__ double g_sum[256];
__device__ double g_sumsq[256];
__device__ float  g_scale[256];
__device__ float  g_shift[256];
__device__ float  g_pool[2 * GG * 128];
__device__ float  g_cnt[2 * GG];
__device__ float  g_fc1o[GG * 256];
__device__ float  g_fc2o[GG * 64];

// ---------------- helpers ---------------------------------------------------
// split fp32 pair into packed bf16 hi (low half = first elem) and bf16 lo
__device__ __forceinline__ void split2(float e0, float e1, uint32_t& hp, uint32_t& lp) {
    asm("cvt.rn.bf16x2.f32 %0, %1, %2;" : "=r"(hp) : "f"(e1), "f"(e0));
    float h0 = __uint_as_float(hp << 16);
    float h1 = __uint_as_float(hp & 0xFFFF0000u);
    float l0 = e0 - h0, l1 = e1 - h1;
    asm("cvt.rn.bf16x2.f32 %0, %1, %2;" : "=r"(lp) : "f"(l1), "f"(l0));
}

__device__ __forceinline__ void mma16816(float* c, const uint32_t* a, const uint32_t* b) {
    asm volatile("mma.sync.aligned.m16n8k16.row.col.f32.bf16.bf16.f32 "
                 "{%0,%1,%2,%3}, {%4,%5,%6,%7}, {%8,%9}, {%0,%1,%2,%3};"
                 : "+f"(c[0]), "+f"(c[1]), "+f"(c[2]), "+f"(c[3])
                 : "r"(a[0]), "r"(a[1]), "r"(a[2]), "r"(a[3]), "r"(b[0]), "r"(b[1]));
}

// ---------------- bf16x3 mma.sync GEMM --------------------------------------
// MODE 0: g_h[N,128] = Aext[N,1024] @ B[1024,128] + bias
// MODE 1: g_z[N,256] = g_agg[N,128] @ B[128,256]  + bias   (grid.y = 2 over N)
// MODE 2: g_h[N,128] = relu( relu(BN(g_z))[N,256] @ B[256,128] + bias + g_h )
#define AS 40   // smem row stride in bf16 elems (80 B)

template <int MODE>
__global__ __launch_bounds__(256)
void mma_gemm(const float* __restrict__ Aext, const float* __restrict__ Bg,
              const float* __restrict__ bias)
{
    constexpr int K   = (MODE == 0) ? 1024 : ((MODE == 1) ? 128 : 256);
    constexpr int LDB = (MODE == 1) ? 256 : 128;
    constexpr int LDC = (MODE == 1) ? 256 : 128;
    const float* A = (MODE == 0) ? Aext : ((MODE == 1) ? g_agg : g_z);
    float* C = (MODE == 1) ? g_z : g_h;

    __shared__ __align__(16) uint16_t Ahi[128 * AS], Alo[128 * AS];
    __shared__ __align__(16) uint16_t Bhi[128 * AS], Blo[128 * AS];

    const int tid  = threadIdx.x;
    const int lane = tid & 31, wid = tid >> 5;
    const int bm = blockIdx.x * 128;
    const int bn = blockIdx.y * 128;
    const int wm = (wid >> 1) * 32;        // warp M offset in tile
    const int wn = (wid & 1) * 64;         // warp N offset in tile
    const int grp = lane >> 2, qid = lane & 3;

    float acc[2][8][4];
#pragma unroll
    for (int mt = 0; mt < 2; mt++)
#pragma unroll
        for (int nt = 0; nt < 8; nt++)
#pragma unroll
            for (int q = 0; q < 4; q++) acc[mt][nt][q] = 0.f;

    const int arow = tid >> 1, ahalf = tid & 1;        // A loader: row, 16-col half
    const int bnid = tid & 127, bkh = (tid >> 7) * 16; // B loader: n col, 16-k half

    for (int k0 = 0; k0 < K; k0 += 32) {
        // ---- load + convert A tile [128 x 32] ----
        {
            const int r = bm + arow;
            float v[16];
            if (r < NN) {
                const float* ap = A + (size_t)r * K + k0 + ahalf * 16;
#pragma unroll
                for (int q = 0; q < 4; q++)
                    *reinterpret_cast<float4*>(v + 4 * q) =
                        __ldg(reinterpret_cast<const float4*>(ap + 4 * q));
            } else {
#pragma unroll
                for (int j = 0; j < 16; j++) v[j] = 0.f;
            }
            if (MODE == 2) {
                const int kb = k0 + ahalf * 16;
#pragma unroll
                for (int j = 0; j < 16; j++)
                    v[j] = fmaxf(fmaf(v[j], g_scale[kb + j], g_shift[kb + j]), 0.f);
            }
#pragma unroll
            for (int q = 0; q < 2; q++) {
                uint32_t hs[4], ls[4];
#pragma unroll
                for (int p = 0; p < 4; p++)
                    split2(v[q * 8 + p * 2], v[q * 8 + p * 2 + 1], hs[p], ls[p]);
                const int c = ahalf * 16 + q * 8;
                *reinterpret_cast<uint4*>(&Ahi[arow * AS + c]) = make_uint4(hs[0], hs[1], hs[2], hs[3]);
                *reinterpret_cast<uint4*>(&Alo[arow * AS + c]) = make_uint4(ls[0], ls[1], ls[2], ls[3]);
            }
        }
        // ---- load + transpose + convert B tile [32 x 128] -> Bs[n][k] ----
        {
            const float* bp = Bg + (size_t)(k0 + bkh) * LDB + bn + bnid;
            float v[16];
#pragma unroll
            for (int j = 0; j < 16; j++) v[j] = __ldg(bp + (size_t)j * LDB);
#pragma unroll
            for (int q = 0; q < 2; q++) {
                uint32_t hs[4], ls[4];
#pragma unroll
                for (int p = 0; p < 4; p++)
                    split2(v[q * 8 + p * 2], v[q * 8 + p * 2 + 1], hs[p], ls[p]);
                const int c = bkh + q * 8;
                *reinterpret_cast<uint4*>(&Bhi[bnid * AS + c]) = make_uint4(hs[0], hs[1], hs[2], hs[3]);
                *reinterpret_cast<uint4*>(&Blo[bnid * AS + c]) = make_uint4(ls[0], ls[1], ls[2], ls[3]);
            }
        }
        __syncthreads();

        // ---- compute: 2 k16 sub-steps ----
#pragma unroll
        for (int s = 0; s < 32; s += 16) {
            uint32_t ah[2][4], al[2][4];
#pragma unroll
            for (int mt = 0; mt < 2; mt++) {
                const int r0 = (wm + mt * 16 + grp) * AS + s + qid * 2;
                const int r8 = r0 + 8 * AS;
                ah[mt][0] = *reinterpret_cast<const uint32_t*>(&Ahi[r0]);
                ah[mt][1] = *reinterpret_cast<const uint32_t*>(&Ahi[r8]);
                ah[mt][2] = *reinterpret_cast<const uint32_t*>(&Ahi[r0 + 8]);
                ah[mt][3] = *reinterpret_cast<const uint32_t*>(&Ahi[r8 + 8]);
                al[mt][0] = *reinterpret_cast<const uint32_t*>(&Alo[r0]);
                al[mt][1] = *reinterpret_cast<const uint32_t*>(&Alo[r8]);
                al[mt][2] = *reinterpret_cast<const uint32_t*>(&Alo[r0 + 8]);
                al[mt][3] = *reinterpret_cast<const uint32_t*>(&Alo[r8 + 8]);
            }
#pragma unroll
            for (int nt = 0; nt < 8; nt++) {
                const int nb = (wn + nt * 8 + grp) * AS + s + qid * 2;
                uint32_t bh[2], bl[2];
                bh[0] = *reinterpret_cast<const uint32_t*>(&Bhi[nb]);
                bh[1] = *reinterpret_cast<const uint32_t*>(&Bhi[nb + 8]);
                bl[0] = *reinterpret_cast<const uint32_t*>(&Blo[nb]);
                bl[1] = *reinterpret_cast<const uint32_t*>(&Blo[nb + 8]);
#pragma unroll
                for (int mt = 0; mt < 2; mt++) {
                    mma16816(acc[mt][nt], ah[mt], bh);   // hi * hi
                    mma16816(acc[mt][nt], ah[mt], bl);   // hi * lo
                    mma16816(acc[mt][nt], al[mt], bh);   // lo * hi
                }
            }
        }
        __syncthreads();
    }

    // ---- epilogue ----
#pragma unroll
    for (int mt = 0; mt < 2; mt++) {
        const int r0 = bm + wm + mt * 16 + grp;
#pragma unroll
        for (int nt = 0; nt < 8; nt++) {
            const int cc = bn + wn + nt * 8 + qid * 2;
            const float b0 = bias[cc], b1 = bias[cc + 1];
#pragma unroll
            for (int hrow = 0; hrow < 2; hrow++) {
                const int r = r0 + hrow * 8;
                if (r < NN) {
                    float2 o;
                    o.x = acc[mt][nt][hrow * 2 + 0] + b0;
                    o.y = acc[mt][nt][hrow * 2 + 1] + b1;
                    if (MODE == 2) {
                        const float2 h = *reinterpret_cast<const float2*>(&g_h[(size_t)r * 128 + cc]);
                        o.x = fmaxf(o.x + h.x, 0.f);
                        o.y = fmaxf(o.y + h.y, 0.f);
                    }
                    *reinterpret_cast<float2*>(&C[(size_t)r * LDC + cc]) = o;
                }
            }
        }
    }
}

// ---------------- small utility kernels -----------------------------------
__global__ void zero_pool_kernel() {
    int i = blockIdx.x * 256 + threadIdx.x;
    g_pool[i] = 0.f;
    if (i < 2 * GG) g_cnt[i] = 0.f;
}

__global__ void init_agg_kernel(const float* __restrict__ eps) {
    int i = blockIdx.x * 256 + threadIdx.x;   // 12500 x 256 float4s
    float e = 1.0f + eps[0];
    float4 v = reinterpret_cast<const float4*>(g_h)[i];
    v.x *= e; v.y *= e; v.z *= e; v.w *= e;
    reinterpret_cast<float4*>(g_agg)[i] = v;
    if (blockIdx.x == 0) { g_sum[threadIdx.x] = 0.0; g_sumsq[threadIdx.x] = 0.0; }
}

__global__ void scatter_kernel(const int* __restrict__ ei) {
    int idx = blockIdx.x * 256 + threadIdx.x;  // 200000 x 256 (== E*32)
    int e = idx >> 5;
    int c = (idx & 31) << 2;
    int src = __ldg(&ei[e]);
    int dst = __ldg(&ei[EE + e]);
    float4 v = *reinterpret_cast<const float4*>(&g_h[src * 128 + c]);
    float* p = &g_agg[dst * 128 + c];
    asm volatile("red.global.add.v4.f32 [%0], {%1,%2,%3,%4};"
                 :: "l"(p), "f"(v.x), "f"(v.y), "f"(v.z), "f"(v.w) : "memory");
}

__global__ void bn_stats_kernel() {     // 391 x 256
    int col = threadIdx.x;
    int r0 = blockIdx.x * 256;
    int r1 = min(r0 + 256, NN);
    float s = 0.f, s2 = 0.f;
    for (int r = r0; r < r1; r++) {
        float v = g_z[(size_t)r * 256 + col];
        s += v;
        s2 = fmaf(v, v, s2);
    }
    atomicAdd(&g_sum[col], (double)s);
    atomicAdd(&g_sumsq[col], (double)s2);
}

__global__ void bn_finalize_kernel(const float* __restrict__ gam,
                                   const float* __restrict__ bet) {
    int c = threadIdx.x;   // 256
    float mean = (float)(g_sum[c] / (double)NN);
    float var  = (float)(g_sumsq[c] / (double)NN) - mean * mean;
    float sc = gam[c] * rsqrtf(var + 1e-5f);
    g_scale[c] = sc;
    g_shift[c] = fmaf(-mean, sc, bet[c]);
}

__global__ void pool_kernel(const int* __restrict__ batch, int which) {
    int idx = blockIdx.x * 256 + threadIdx.x;   // 12500 x 256 (== N*32)
    int n = idx >> 5;
    int c = (idx & 31) << 2;
    int g = __ldg(&batch[n]);
    float4 v = *reinterpret_cast<const float4*>(&g_h[n * 128 + c]);
    float* p = &g_pool[(which * GG + g) * 128 + c];
    asm volatile("red.global.add.v4.f32 [%0], {%1,%2,%3,%4};"
                 :: "l"(p), "f"(v.x), "f"(v.y), "f"(v.z), "f"(v.w) : "memory");
    if ((idx & 31) == 0) atomicAdd(&g_cnt[which * GG + g], 1.0f);
}

__global__ void head1_kernel(const float* __restrict__ W, const float* __restrict__ b) {
    int g = blockIdx.x, j = threadIdx.x;   // 64 x 256
    __shared__ float xc[256];
    if (j < 128) xc[j] = g_pool[g * 128 + j] / fmaxf(g_cnt[g], 1.0f);
    else         xc[j] = g_pool[(GG + g) * 128 + (j - 128)] / fmaxf(g_cnt[GG + g], 1.0f);
    __syncthreads();
    float acc = b[j];
#pragma unroll 8
    for (int k = 0; k < 256; k++) acc = fmaf(xc[k], W[k * 256 + j], acc);
    g_fc1o[g * 256 + j] = fmaxf(acc, 0.f);
}

__global__ void head2_kernel(const float* __restrict__ W, const float* __restrict__ b) {
    int g = blockIdx.x, j = threadIdx.x;   // 64 x 64
    __shared__ float xin[256];
    for (int k = j; k < 256; k += 64) xin[k] = g_fc1o[g * 256 + k];
    __syncthreads();
    float acc = b[j];
#pragma unroll 8
    for (int k = 0; k < 256; k++) acc = fmaf(xin[k], W[k * 64 + j], acc);
    g_fc2o[g * 64 + j] = fmaxf(acc, 0.f);
}

__global__ void head3_kernel(const float* __restrict__ W, const float* __restrict__ b,
                             float* __restrict__ out) {
    int g = threadIdx.x;   // 1 x 64
    float acc = b[0];
#pragma unroll
    for (int k = 0; k < 64; k++) acc = fmaf(g_fc2o[g * 64 + k], W[k], acc);
    out[g] = 1.0f / (1.0f + expf(-acc));
}

// ---------------- orchestration -------------------------------------------
extern "C" void kernel_launch(void* const* d_in, const int* in_sizes, int n_in,
                              void* d_out, int out_size) {
    const float* x[2]     = { (const float*)d_in[0], (const float*)d_in[3] };
    const int*   ei[2]    = { (const int*)d_in[1],   (const int*)d_in[4] };
    const int*   batch[2] = { (const int*)d_in[2],   (const int*)d_in[5] };

    const int GRID_M = (NN + 127) / 128;   // 782

    zero_pool_kernel<<<64, 256>>>();

    for (int b = 0; b < 2; b++) {
        int o = 6 + b * 9;
        const float* embW = (const float*)d_in[o + 0];
        const float* embB = (const float*)d_in[o + 1];
        const float* W1   = (const float*)d_in[o + 2];
        const float* b1   = (const float*)d_in[o + 3];
        const float* gam  = (const float*)d_in[o + 4];
        const float* bet  = (const float*)d_in[o + 5];
        const float* W2   = (const float*)d_in[o + 6];
        const float* b2   = (const float*)d_in[o + 7];
        const float* eps  = (const float*)d_in[o + 8];

        mma_gemm<0><<<dim3(GRID_M, 1), 256>>>(x[b], embW, embB);

        for (int i = 0; i < 4; i++) {
            init_agg_kernel<<<12500, 256>>>(eps + i);
            scatter_kernel<<<200000, 256>>>(ei[b]);
            mma_gemm<1><<<dim3(GRID_M, 2), 256>>>(nullptr, W1 + (size_t)i * 128 * 256,
                                                  b1 + i * 256);
            bn_stats_kernel<<<391, 256>>>();
            bn_finalize_kernel<<<1, 256>>>(gam + i * 256, bet + i * 256);
            mma_gemm<2><<<dim3(GRID_M, 1), 256>>>(nullptr, W2 + (size_t)i * 256 * 128,
                                                  b2 + i * 128);
        }
        pool_kernel<<<12500, 256>>>(batch[b], b);
    }

    head1_kernel<<<64, 256>>>((const float*)d_in[24], (const float*)d_in[25]);
    head2_kernel<<<64, 64>>>((const float*)d_in[26], (const float*)d_in[27]);
    head3_kernel<<<1, 64>>>((const float*)d_in[28], (const float*)d_in[29], (float*)d_out);
}

// round 5
// speedup vs baseline: 1.2842x; 1.0591x over previous
#include <cuda_runtime.h>
#include <math.h>
#include <stdint.h>

#define NN 100000
#define EE 1600000
#define GG 64

// ---------------- scratch (device globals; no allocation allowed) ----------
__device__ float  g_h[NN * 128];
__device__ float  g_agg[NN * 128];
__device__ float  g_z[NN * 256];
__device__ double g_sum[256];
__device__ double g_sumsq[256];
__device__ float  g_scale[256];
__device__ float  g_shift[256];
__device__ float  g_pool[2 * GG * 128];
__device__ float  g_cnt[2 * GG];
__device__ float  g_fc1o[GG * 256];
__device__ float  g_fc2o[GG * 64];

// ---------------- helpers ---------------------------------------------------
__device__ __forceinline__ void split2(float e0, float e1, uint32_t& hp, uint32_t& lp) {
    asm("cvt.rn.bf16x2.f32 %0, %1, %2;" : "=r"(hp) : "f"(e1), "f"(e0));
    float h0 = __uint_as_float(hp << 16);
    float h1 = __uint_as_float(hp & 0xFFFF0000u);
    float l0 = e0 - h0, l1 = e1 - h1;
    asm("cvt.rn.bf16x2.f32 %0, %1, %2;" : "=r"(lp) : "f"(l1), "f"(l0));
}

__device__ __forceinline__ void mma16816(float* c, const uint32_t* a, const uint32_t* b) {
    asm volatile("mma.sync.aligned.m16n8k16.row.col.f32.bf16.bf16.f32 "
                 "{%0,%1,%2,%3}, {%4,%5,%6,%7}, {%8,%9}, {%0,%1,%2,%3};"
                 : "+f"(c[0]), "+f"(c[1]), "+f"(c[2]), "+f"(c[3])
                 : "r"(a[0]), "r"(a[1]), "r"(a[2]), "r"(a[3]), "r"(b[0]), "r"(b[1]));
}

// ---------------- bf16x3 mma.sync GEMM, prefetch-pipelined -------------------
// MODE 0: g_h[N,128] = Aext[N,1024] @ B[1024,128] + bias
// MODE 1: g_z[N,256] = (g_agg + (1+eps)*g_h)[N,128] @ B[128,256] + bias  (grid.y=2)
// MODE 2: g_h[N,128] = relu( relu(BN(g_z))[N,256] @ B[256,128] + bias + g_h )
#define AS 40   // smem row stride in bf16 elems (80 B)

template <int MODE>
__global__ __launch_bounds__(256)
void mma_gemm(const float* __restrict__ Aext, const float* __restrict__ Bg,
              const float* __restrict__ bias, const float* __restrict__ epsp)
{
    constexpr int K   = (MODE == 0) ? 1024 : ((MODE == 1) ? 128 : 256);
    constexpr int LDB = (MODE == 1) ? 256 : 128;
    constexpr int LDC = (MODE == 1) ? 256 : 128;
    constexpr int NCHUNK = K / 32;
    const float* A = (MODE == 0) ? Aext : ((MODE == 1) ? g_agg : g_z);
    float* C = (MODE == 1) ? g_z : g_h;

    __shared__ __align__(16) uint16_t Ahi[128 * AS], Alo[128 * AS];
    __shared__ __align__(16) uint16_t Bhi[128 * AS], Blo[128 * AS];

    const int tid  = threadIdx.x;
    const int lane = tid & 31, wid = tid >> 5;
    const int bm = blockIdx.x * 128;
    const int bn = blockIdx.y * 128;
    const int wm = (wid >> 1) * 32;
    const int wn = (wid & 1) * 64;
    const int grp = lane >> 2, qid = lane & 3;

    if (MODE == 1 && blockIdx.x == 0 && blockIdx.y == 0) {
        g_sum[tid] = 0.0; g_sumsq[tid] = 0.0;   // safe: completes before bn_stats launch
    }
    const float ee = (MODE == 1) ? (1.0f + __ldg(epsp)) : 0.0f;

    float acc[2][8][4];
#pragma unroll
    for (int mt = 0; mt < 2; mt++)
#pragma unroll
        for (int nt = 0; nt < 8; nt++)
#pragma unroll
            for (int q = 0; q < 4; q++) acc[mt][nt][q] = 0.f;

    const int arow = tid >> 1, ahalf = tid & 1;        // A loader: row, 16-col half
    const int bnid = tid & 127, bkh = (tid >> 7) * 16; // B loader: n col, 16-k half
    const int rA = bm + arow;

    // ---- loaders (registers only) ----
    auto loadA = [&](int k0, float* v) {
        if (rA < NN) {
            const float* ap = A + (size_t)rA * K + k0 + ahalf * 16;
#pragma unroll
            for (int q = 0; q < 4; q++)
                *reinterpret_cast<float4*>(v + 4 * q) =
                    __ldg(reinterpret_cast<const float4*>(ap + 4 * q));
            if (MODE == 1) {
                const float* hp = g_h + (size_t)rA * 128 + k0 + ahalf * 16;
#pragma unroll
                for (int q = 0; q < 4; q++) {
                    float4 hv = __ldg(reinterpret_cast<const float4*>(hp + 4 * q));
                    v[4 * q + 0] = fmaf(ee, hv.x, v[4 * q + 0]);
                    v[4 * q + 1] = fmaf(ee, hv.y, v[4 * q + 1]);
                    v[4 * q + 2] = fmaf(ee, hv.z, v[4 * q + 2]);
                    v[4 * q + 3] = fmaf(ee, hv.w, v[4 * q + 3]);
                }
            }
        } else {
#pragma unroll
            for (int j = 0; j < 16; j++) v[j] = 0.f;
        }
        if (MODE == 2) {
            const int kb = k0 + ahalf * 16;
#pragma unroll
            for (int j = 0; j < 16; j++)
                v[j] = fmaxf(fmaf(v[j], g_scale[kb + j], g_shift[kb + j]), 0.f);
        }
    };
    auto loadB = [&](int k0, float* v) {
        const float* bp = Bg + (size_t)(k0 + bkh) * LDB + bn + bnid;
#pragma unroll
        for (int j = 0; j < 16; j++) v[j] = __ldg(bp + (size_t)j * LDB);
    };
    auto storeA = [&](const float* v) {
#pragma unroll
        for (int q = 0; q < 2; q++) {
            uint32_t hs[4], ls[4];
#pragma unroll
            for (int p = 0; p < 4; p++)
                split2(v[q * 8 + p * 2], v[q * 8 + p * 2 + 1], hs[p], ls[p]);
            const int c = ahalf * 16 + q * 8;
            *reinterpret_cast<uint4*>(&Ahi[arow * AS + c]) = make_uint4(hs[0], hs[1], hs[2], hs[3]);
            *reinterpret_cast<uint4*>(&Alo[arow * AS + c]) = make_uint4(ls[0], ls[1], ls[2], ls[3]);
        }
    };
    auto storeB = [&](const float* v) {
#pragma unroll
        for (int q = 0; q < 2; q++) {
            uint32_t hs[4], ls[4];
#pragma unroll
            for (int p = 0; p < 4; p++)
                split2(v[q * 8 + p * 2], v[q * 8 + p * 2 + 1], hs[p], ls[p]);
            const int c = bkh + q * 8;
            *reinterpret_cast<uint4*>(&Bhi[bnid * AS + c]) = make_uint4(hs[0], hs[1], hs[2], hs[3]);
            *reinterpret_cast<uint4*>(&Blo[bnid * AS + c]) = make_uint4(ls[0], ls[1], ls[2], ls[3]);
        }
    };
    auto mmaStep = [&]() {
#pragma unroll
        for (int s = 0; s < 32; s += 16) {
            uint32_t ah[2][4], al[2][4];
#pragma unroll
            for (int mt = 0; mt < 2; mt++) {
                const int r0 = (wm + mt * 16 + grp) * AS + s + qid * 2;
                const int r8 = r0 + 8 * AS;
                ah[mt][0] = *reinterpret_cast<const uint32_t*>(&Ahi[r0]);
                ah[mt][1] = *reinterpret_cast<const uint32_t*>(&Ahi[r8]);
                ah[mt][2] = *reinterpret_cast<const uint32_t*>(&Ahi[r0 + 8]);
                ah[mt][3] = *reinterpret_cast<const uint32_t*>(&Ahi[r8 + 8]);
                al[mt][0] = *reinterpret_cast<const uint32_t*>(&Alo[r0]);
                al[mt][1] = *reinterpret_cast<const uint32_t*>(&Alo[r8]);
                al[mt][2] = *reinterpret_cast<const uint32_t*>(&Alo[r0 + 8]);
                al[mt][3] = *reinterpret_cast<const uint32_t*>(&Alo[r8 + 8]);
            }
#pragma unroll
            for (int nt = 0; nt < 8; nt++) {
                const int nb = (wn + nt * 8 + grp) * AS + s + qid * 2;
                uint32_t bh[2], bl[2];
                bh[0] = *reinterpret_cast<const uint32_t*>(&Bhi[nb]);
                bh[1] = *reinterpret_cast<const uint32_t*>(&Bhi[nb + 8]);
                bl[0] = *reinterpret_cast<const uint32_t*>(&Blo[nb]);
                bl[1] = *reinterpret_cast<const uint32_t*>(&Blo[nb + 8]);
#pragma unroll
                for (int mt = 0; mt < 2; mt++) {
                    mma16816(acc[mt][nt], ah[mt], bh);
                    mma16816(acc[mt][nt], ah[mt], bl);
                    mma16816(acc[mt][nt], al[mt], bh);
                }
            }
        }
    };

    // ---- prologue: chunk 0 ----
    {
        float va[16], vb[16];
        loadA(0, va); loadB(0, vb);
        storeA(va);   storeB(vb);
    }
    __syncthreads();

    // ---- pipelined main loop ----
    for (int ch = 0; ch < NCHUNK - 1; ch++) {
        float wa[16], wb[16];
        loadA((ch + 1) * 32, wa);       // LDGs issue here, overlap MMA below
        loadB((ch + 1) * 32, wb);
        mmaStep();
        __syncthreads();                // all warps done reading smem
        storeA(wa); storeB(wb);
        __syncthreads();                // smem ready
    }
    mmaStep();                          // last chunk

    // ---- epilogue ----
#pragma unroll
    for (int mt = 0; mt < 2; mt++) {
        const int r0 = bm + wm + mt * 16 + grp;
#pragma unroll
        for (int nt = 0; nt < 8; nt++) {
            const int cc = bn + wn + nt * 8 + qid * 2;
            const float b0 = bias[cc], b1 = bias[cc + 1];
#pragma unroll
            for (int hrow = 0; hrow < 2; hrow++) {
                const int r = r0 + hrow * 8;
                if (r < NN) {
                    float2 o;
                    o.x = acc[mt][nt][hrow * 2 + 0] + b0;
                    o.y = acc[mt][nt][hrow * 2 + 1] + b1;
                    if (MODE == 2) {
                        const float2 h = *reinterpret_cast<const float2*>(&g_h[(size_t)r * 128 + cc]);
                        o.x = fmaxf(o.x + h.x, 0.f);
                        o.y = fmaxf(o.y + h.y, 0.f);
                    }
                    *reinterpret_cast<float2*>(&C[(size_t)r * LDC + cc]) = o;
                }
            }
        }
    }
}

// ---------------- small utility kernels -----------------------------------
__global__ void zero_pool_kernel() {
    int i = blockIdx.x * 256 + threadIdx.x;
    g_pool[i] = 0.f;
    if (i < 2 * GG) g_cnt[i] = 0.f;
}

__global__ void scatter_kernel(const int* __restrict__ ei) {
    int idx = blockIdx.x * 256 + threadIdx.x;  // 200000 x 256 (== E*32)
    int e = idx >> 5;
    int c = (idx & 31) << 2;
    int src = __ldg(&ei[e]);
    int dst = __ldg(&ei[EE + e]);
    float4 v = *reinterpret_cast<const float4*>(&g_h[src * 128 + c]);
    float* p = &g_agg[dst * 128 + c];
    asm volatile("red.global.add.v4.f32 [%0], {%1,%2,%3,%4};"
                 :: "l"(p), "f"(v.x), "f"(v.y), "f"(v.z), "f"(v.w) : "memory");
}

__global__ void bn_stats_kernel() {     // 391 x 256
    int col = threadIdx.x;
    int r0 = blockIdx.x * 256;
    int r1 = min(r0 + 256, NN);
    float s = 0.f, s2 = 0.f;
    for (int r = r0; r < r1; r++) {
        float v = g_z[(size_t)r * 256 + col];
        s += v;
        s2 = fmaf(v, v, s2);
    }
    atomicAdd(&g_sum[col], (double)s);
    atomicAdd(&g_sumsq[col], (double)s2);
}

__global__ void bn_finalize_kernel(const float* __restrict__ gam,
                                   const float* __restrict__ bet) {
    int c = threadIdx.x;   // 256
    float mean = (float)(g_sum[c] / (double)NN);
    float var  = (float)(g_sumsq[c] / (double)NN) - mean * mean;
    float sc = gam[c] * rsqrtf(var + 1e-5f);
    g_scale[c] = sc;
    g_shift[c] = fmaf(-mean, sc, bet[c]);
}

__global__ void pool_kernel(const int* __restrict__ batch, int which) {
    int idx = blockIdx.x * 256 + threadIdx.x;   // 12500 x 256 (== N*32)
    int n = idx >> 5;
    int c = (idx & 31) << 2;
    int g = __ldg(&batch[n]);
    float4 v = *reinterpret_cast<const float4*>(&g_h[n * 128 + c]);
    float* p = &g_pool[(which * GG + g) * 128 + c];
    asm volatile("red.global.add.v4.f32 [%0], {%1,%2,%3,%4};"
                 :: "l"(p), "f"(v.x), "f"(v.y), "f"(v.z), "f"(v.w) : "memory");
    if ((idx & 31) == 0) atomicAdd(&g_cnt[which * GG + g], 1.0f);
}

__global__ void head1_kernel(const float* __restrict__ W, const float* __restrict__ b) {
    int g = blockIdx.x, j = threadIdx.x;   // 64 x 256
    __shared__ float xc[256];
    if (j < 128) xc[j] = g_pool[g * 128 + j] / fmaxf(g_cnt[g], 1.0f);
    else         xc[j] = g_pool[(GG + g) * 128 + (j - 128)] / fmaxf(g_cnt[GG + g], 1.0f);
    __syncthreads();
    float acc = b[j];
#pragma unroll 8
    for (int k = 0; k < 256; k++) acc = fmaf(xc[k], W[k * 256 + j], acc);
    g_fc1o[g * 256 + j] = fmaxf(acc, 0.f);
}

__global__ void head2_kernel(const float* __restrict__ W, const float* __restrict__ b) {
    int g = blockIdx.x, j = threadIdx.x;   // 64 x 64
    __shared__ float xin[256];
    for (int k = j; k < 256; k += 64) xin[k] = g_fc1o[g * 256 + k];
    __syncthreads();
    float acc = b[j];
#pragma unroll 8
    for (int k = 0; k < 256; k++) acc = fmaf(xin[k], W[k * 64 + j], acc);
    g_fc2o[g * 64 + j] = fmaxf(acc, 0.f);
}

__global__ void head3_kernel(const float* __restrict__ W, const float* __restrict__ b,
                             float* __restrict__ out) {
    int g = threadIdx.x;   // 1 x 64
    float acc = b[0];
#pragma unroll
    for (int k = 0; k < 64; k++) acc = fmaf(g_fc2o[g * 64 + k], W[k], acc);
    out[g] = 1.0f / (1.0f + expf(-acc));
}

// ---------------- orchestration -------------------------------------------
extern "C" void kernel_launch(void* const* d_in, const int* in_sizes, int n_in,
                              void* d_out, int out_size) {
    const float* x[2]     = { (const float*)d_in[0], (const float*)d_in[3] };
    const int*   ei[2]    = { (const int*)d_in[1],   (const int*)d_in[4] };
    const int*   batch[2] = { (const int*)d_in[2],   (const int*)d_in[5] };

    void* aggp = nullptr;
    cudaGetSymbolAddress(&aggp, g_agg);

    const int GRID_M = (NN + 127) / 128;   // 782

    zero_pool_kernel<<<64, 256>>>();

    for (int b = 0; b < 2; b++) {
        int o = 6 + b * 9;
        const float* embW = (const float*)d_in[o + 0];
        const float* embB = (const float*)d_in[o + 1];
        const float* W1   = (const float*)d_in[o + 2];
        const float* b1   = (const float*)d_in[o + 3];
        const float* gam  = (const float*)d_in[o + 4];
        const float* bet  = (const float*)d_in[o + 5];
        const float* W2   = (const float*)d_in[o + 6];
        const float* b2   = (const float*)d_in[o + 7];
        const float* eps  = (const float*)d_in[o + 8];

        mma_gemm<0><<<dim3(GRID_M, 1), 256>>>(x[b], embW, embB, nullptr);

        for (int i = 0; i < 4; i++) {
            cudaMemsetAsync(aggp, 0, (size_t)NN * 128 * sizeof(float), 0);
            scatter_kernel<<<200000, 256>>>(ei[b]);
            mma_gemm<1><<<dim3(GRID_M, 2), 256>>>(nullptr, W1 + (size_t)i * 128 * 256,
                                                  b1 + i * 256, eps + i);
            bn_stats_kernel<<<391, 256>>>();
            bn_finalize_kernel<<<1, 256>>>(gam + i * 256, bet + i * 256);
            mma_gemm<2><<<dim3(GRID_M, 1), 256>>>(nullptr, W2 + (size_t)i * 256 * 128,
                                                  b2 + i * 128, nullptr);
        }
        pool_kernel<<<12500, 256>>>(batch[b], b);
    }

    head1_kernel<<<64, 256>>>((const float*)d_in[24], (const float*)d_in[25]);
    head2_kernel<<<64, 64>>>((const float*)d_in[26], (const float*)d_in[27]);
    head3_kernel<<<1, 64>>>((const float*)d_in[28], (const float*)d_in[29], (float*)d_out);
}